// round 6
// baseline (speedup 1.0000x reference)
#include <cuda_runtime.h>
#include <cstdint>

#define K3          27
#define PAIRS_PER_K 131072
#define N_VOX       262144
#define C_IN        32
#define C_OUT       32
#define M_TOTAL     (K3 * PAIRS_PER_K)

#define TILE        128                     // pairs per MMA tile (8 warps x 16)
#define NT          8                       // tiles per block (same k)
#define TPB         256
#define TILES_PER_K (PAIRS_PER_K / TILE)    // 1024 (divisible by NT)
#define GRID        (M_TOTAL / TILE / NT)   // 3456
#define RS          36                      // A smem row stride in floats (144B)

// ---------------------------------------------------------------------------
// Kernel 1: initialize output with bias (d_out is poisoned by harness).
// ---------------------------------------------------------------------------
__global__ void init_bias_kernel(float4* __restrict__ out,
                                 const float4* __restrict__ bias4) {
    int t = blockIdx.x * blockDim.x + threadIdx.x;
    if (t < N_VOX * 8) out[t] = bias4[t & 7];
}

__device__ __forceinline__ uint32_t f2tf32(float x) {
    uint32_t r;
    asm("cvt.rna.tf32.f32 %0, %1;" : "=r"(r) : "f"(x));
    return r;
}

// ---------------------------------------------------------------------------
// Kernel 2: cp.async gather -> tf32 mma.sync (m16n8k8, B frags from a
// per-lane smem table, A fed as raw f32 bits = RZ tf32) -> shfl-merged
// coalesced red.global.add.v4 scatter.  5 CTAs/SM (40 warps).
// ---------------------------------------------------------------------------
__global__ void __launch_bounds__(TPB, 5)
conv_mma_kernel(const float* __restrict__ in_feature,   // [N_VOX][32]
                const float* __restrict__ kernel_w,     // [K3][32][32]
                const int*   __restrict__ nbmap,        // [M][2] (src,dst)
                float*       __restrict__ out)          // [N_VOX][32]
{
    __shared__ __align__(16) float As[2][TILE * RS];    // 2 x 18432B
    __shared__ __align__(16) uint2 Bsm[512];            // 4KB: [(j*4+s)*32+lane]

    const int tid  = threadIdx.x;
    const int wid  = tid >> 5;
    const int lane = tid & 31;

    const int tile0 = blockIdx.x * NT;
    const int k     = tile0 / TILES_PER_K;

    // ---- Build per-lane B fragment table (once per block, RNA tf32) ----
    {
        const float* wk = kernel_w + (size_t)k * (C_IN * C_OUT);
#pragma unroll
        for (int r = 0; r < 2; r++) {
            const int e  = tid + 256 * r;
            const int el = e & 31, s = (e >> 5) & 3, j = e >> 7;
            const int bk = el & 3, bn = el >> 2;
            uint2 b;
            b.x = f2tf32(wk[(8 * s + bk    ) * C_OUT + 8 * j + bn]);
            b.y = f2tf32(wk[(8 * s + bk + 4) * C_OUT + 8 * j + bn]);
            Bsm[e] = b;
        }
    }

    // ---- gather tile t into buffer buf: 1024 x cp.async.cg 16B ----
    auto gather = [&](int t, int buf) {
        const size_t pbase = (size_t)(tile0 + t) * TILE;
        const int ch = tid & 7;
#pragma unroll
        for (int jj = 0; jj < 4; jj++) {
            const int row = (tid >> 3) + 32 * jj;
            const int v   = nbmap[2 * (pbase + row)];         // src voxel
            const float* src = in_feature + (size_t)v * C_IN + ch * 4;
            const uint32_t dst =
                (uint32_t)__cvta_generic_to_shared(&As[buf][row * RS + ch * 4]);
            asm volatile("cp.async.cg.shared.global [%0], [%1], 16;"
                         :: "r"(dst), "l"(src));
        }
        asm volatile("cp.async.commit_group;" ::: "memory");
    };

    gather(0, 0);

    const int ar   = lane >> 2;                       // frag row-in-8
    const int ac   = lane & 3;                        // frag col-in-4
    const int rloc = 16 * wid + ar + 8 * (lane & 1);  // this lane's output row
    const int colb = (lane & 2) << 1;                 // 0 or 4
    const bool odd = lane & 1;

    for (int t = 0; t < NT; t++) {
        const int buf = t & 1;
        asm volatile("cp.async.wait_group 0;" ::: "memory");
        __syncthreads();                              // A(t) + Bsm ready

        if (t + 1 < NT) gather(t + 1, buf ^ 1);       // overlap with compute

        // destination voxel for this lane's merged row
        const int y = nbmap[2 * ((size_t)(tile0 + t) * TILE + rloc) + 1];
        float* orow = out + (size_t)y * C_OUT + colb;

        // A fragments: raw f32 bits (HW reads tf32 = truncated f32).
        const uint32_t* Ab = reinterpret_cast<const uint32_t*>(
            &As[buf][(16 * wid + ar) * RS]);
        uint32_t A0[4], A1[4], A2[4], A3[4];
#pragma unroll
        for (int s = 0; s < 4; s++) {
            A0[s] = Ab[8 * s + ac];
            A1[s] = Ab[8 * RS + 8 * s + ac];
            A2[s] = Ab[8 * s + ac + 4];
            A3[s] = Ab[8 * RS + 8 * s + ac + 4];
        }

#pragma unroll
        for (int j = 0; j < 4; j++) {
            float D0 = 0.f, D1 = 0.f, D2 = 0.f, D3 = 0.f;
#pragma unroll
            for (int s = 0; s < 4; s++) {
                const uint2 b = Bsm[(j * 4 + s) * 32 + lane];
                asm volatile(
                    "mma.sync.aligned.m16n8k8.row.col.f32.tf32.tf32.f32 "
                    "{%0,%1,%2,%3}, {%4,%5,%6,%7}, {%8,%9}, {%0,%1,%2,%3};"
                    : "+f"(D0), "+f"(D1), "+f"(D2), "+f"(D3)
                    : "r"(A0[s]), "r"(A1[s]), "r"(A2[s]), "r"(A3[s]),
                      "r"(b.x), "r"(b.y));
            }
            // bfly-merge this j's D halves into one float4 per lane, then red.
            float s0 = __shfl_xor_sync(0xffffffffu, odd ? D0 : D2, 1);
            float s1 = __shfl_xor_sync(0xffffffffu, odd ? D1 : D3, 1);
            float v0 = odd ? s0 : D0;
            float v1 = odd ? s1 : D1;
            float v2 = odd ? D2 : s0;
            float v3 = odd ? D3 : s1;
            asm volatile("red.global.add.v4.f32 [%0], {%1,%2,%3,%4};"
                         :: "l"(orow + 8 * j), "f"(v0), "f"(v1), "f"(v2), "f"(v3)
                         : "memory");
        }
    }
}

// ---------------------------------------------------------------------------
// Inputs (metadata order): in_feature f32[N_VOX,32], kernel f32[27,32,32],
// bias f32[32], nbmap i32[M,2], nbsizes i32[27]. Output f32[N_VOX,32].
// ---------------------------------------------------------------------------
extern "C" void kernel_launch(void* const* d_in, const int* in_sizes, int n_in,
                              void* d_out, int out_size) {
    const float*  in_feature = (const float*)d_in[0];
    const float*  kernel_w   = (const float*)d_in[1];
    const float4* bias4      = (const float4*)d_in[2];
    const int*    nbmap      = (const int*)d_in[3];
    float*        out        = (float*)d_out;

    init_bias_kernel<<<(N_VOX * 8 + 255) / 256, 256>>>((float4*)out, bias4);
    conv_mma_kernel<<<GRID, TPB>>>(in_feature, kernel_w, nbmap, out);
}

// round 7
// speedup vs baseline: 1.1126x; 1.1126x over previous
#include <cuda_runtime.h>
#include <cstdint>

#define K3          27
#define PAIRS_PER_K 131072
#define N_VOX       262144
#define C_IN        32
#define C_OUT       32
#define M_TOTAL     (K3 * PAIRS_PER_K)

#define TILE        128                     // pairs per MMA tile (8 warps x 16)
#define NT          8                       // tiles per block (same k)
#define TPB         256
#define TILES_PER_K (PAIRS_PER_K / TILE)    // 1024 (divisible by NT)
#define GRID        (M_TOTAL / TILE / NT)   // 3456
#define RS          36                      // A smem row stride in floats (144B)

// ---------------------------------------------------------------------------
// Kernel 1: initialize output with bias (d_out is poisoned by harness).
// ---------------------------------------------------------------------------
__global__ void init_bias_kernel(float4* __restrict__ out,
                                 const float4* __restrict__ bias4) {
    int t = blockIdx.x * blockDim.x + threadIdx.x;
    if (t < N_VOX * 8) out[t] = bias4[t & 7];
}

__device__ __forceinline__ uint32_t f2tf32(float x) {
    uint32_t r;
    asm("cvt.rna.tf32.f32 %0, %1;" : "=r"(r) : "f"(x));
    return r;
}

// ---------------------------------------------------------------------------
// Kernel 2: cp.async gather -> tf32 mma.sync (m16n8k8) -> D staged to smem
// (A buffer reuse) -> fully line-coalesced red.global.add.v4 scatter:
// 8 consecutive lanes cover one complete 128B output row.
// ---------------------------------------------------------------------------
__global__ void __launch_bounds__(TPB, 5)
conv_mma_kernel(const float* __restrict__ in_feature,   // [N_VOX][32]
                const float* __restrict__ kernel_w,     // [K3][32][32]
                const int*   __restrict__ nbmap,        // [M][2] (src,dst)
                float*       __restrict__ out)          // [N_VOX][32]
{
    __shared__ __align__(16) float As[2][TILE * RS];    // 2 x 18432B
    __shared__ __align__(16) uint2 Bsm[512];            // 4KB: [(j*4+s)*32+lane]

    const int tid  = threadIdx.x;
    const int wid  = tid >> 5;
    const int lane = tid & 31;

    const int tile0 = blockIdx.x * NT;
    const int k     = tile0 / TILES_PER_K;

    // ---- Build per-lane B fragment table (once per block, RNA tf32) ----
    {
        const float* wk = kernel_w + (size_t)k * (C_IN * C_OUT);
#pragma unroll
        for (int r = 0; r < 2; r++) {
            const int e  = tid + 256 * r;
            const int el = e & 31, s = (e >> 5) & 3, j = e >> 7;
            const int bk = el & 3, bn = el >> 2;
            uint2 b;
            b.x = f2tf32(wk[(8 * s + bk    ) * C_OUT + 8 * j + bn]);
            b.y = f2tf32(wk[(8 * s + bk + 4) * C_OUT + 8 * j + bn]);
            Bsm[e] = b;
        }
    }

    // ---- gather tile t into buffer buf: 1024 x cp.async.cg 16B ----
    auto gather = [&](int t, int buf) {
        const size_t pbase = (size_t)(tile0 + t) * TILE;
        const int ch = tid & 7;
#pragma unroll
        for (int jj = 0; jj < 4; jj++) {
            const int row = (tid >> 3) + 32 * jj;
            const int v   = nbmap[2 * (pbase + row)];         // src voxel
            const uint32_t dst =
                (uint32_t)__cvta_generic_to_shared(&As[buf][row * RS + ch * 4]);
            asm volatile("cp.async.cg.shared.global [%0], [%1], 16;"
                         :: "r"(dst), "l"(in_feature + (size_t)v * C_IN + ch * 4));
        }
        asm volatile("cp.async.commit_group;" ::: "memory");
    };

    gather(0, 0);

    const int ar = lane >> 2;                       // frag row-in-8
    const int ac = lane & 3;                        // frag col-in-4

    for (int t = 0; t < NT; t++) {
        const int buf = t & 1;
        asm volatile("cp.async.wait_group 0;" ::: "memory");
        __syncthreads();                            // A(t) + Bsm ready

        if (t + 1 < NT) gather(t + 1, buf ^ 1);     // overlap with compute

        // A fragments: raw f32 bits (HW reads tf32 = truncated f32).
        const uint32_t* Ab = reinterpret_cast<const uint32_t*>(
            &As[buf][(16 * wid + ar) * RS]);
        uint32_t A0[4], A1[4], A2[4], A3[4];
#pragma unroll
        for (int s = 0; s < 4; s++) {
            A0[s] = Ab[8 * s + ac];
            A1[s] = Ab[8 * RS + 8 * s + ac];
            A2[s] = Ab[8 * s + ac + 4];
            A3[s] = Ab[8 * RS + 8 * s + ac + 4];
        }
        __syncwarp();   // all lanes' A reads done before D overwrites the buffer

#pragma unroll
        for (int j = 0; j < 4; j++) {
            float D0 = 0.f, D1 = 0.f, D2 = 0.f, D3 = 0.f;
#pragma unroll
            for (int s = 0; s < 4; s++) {
                const uint2 b = Bsm[(j * 4 + s) * 32 + lane];
                asm volatile(
                    "mma.sync.aligned.m16n8k8.row.col.f32.tf32.tf32.f32 "
                    "{%0,%1,%2,%3}, {%4,%5,%6,%7}, {%8,%9}, {%0,%1,%2,%3};"
                    : "+f"(D0), "+f"(D1), "+f"(D2), "+f"(D3)
                    : "r"(A0[s]), "r"(A1[s]), "r"(A2[s]), "r"(A3[s]),
                      "r"(b.x), "r"(b.y));
            }
            // Stage D fragments into the (now consumed) A buffer, warp-private
            // rows: {D0,D1} -> (row 16wid+ar, col 2ac+8j), {D2,D3} -> row+8.
            *reinterpret_cast<float2*>(
                &As[buf][(16 * wid + ar)     * RS + 2 * ac + 8 * j]) =
                make_float2(D0, D1);
            *reinterpret_cast<float2*>(
                &As[buf][(16 * wid + ar + 8) * RS + 2 * ac + 8 * j]) =
                make_float2(D2, D3);
        }
        __syncwarp();

        // Line-coalesced scatter: lanes 0-7 cover one full 128B output row.
        const size_t pbase = (size_t)(tile0 + t) * TILE;
        const int chunk = lane & 7;
#pragma unroll
        for (int ii = 0; ii < 4; ii++) {
            const int row = 16 * wid + (lane >> 3) + 4 * ii;
            const int y   = nbmap[2 * (pbase + row) + 1];
            const float4 v = *reinterpret_cast<const float4*>(
                &As[buf][row * RS + chunk * 4]);
            asm volatile("red.global.add.v4.f32 [%0], {%1,%2,%3,%4};"
                         :: "l"(out + (size_t)y * C_OUT + chunk * 4),
                            "f"(v.x), "f"(v.y), "f"(v.z), "f"(v.w)
                         : "memory");
        }
    }
}

// ---------------------------------------------------------------------------
// Inputs (metadata order): in_feature f32[N_VOX,32], kernel f32[27,32,32],
// bias f32[32], nbmap i32[M,2], nbsizes i32[27]. Output f32[N_VOX,32].
// ---------------------------------------------------------------------------
extern "C" void kernel_launch(void* const* d_in, const int* in_sizes, int n_in,
                              void* d_out, int out_size) {
    const float*  in_feature = (const float*)d_in[0];
    const float*  kernel_w   = (const float*)d_in[1];
    const float4* bias4      = (const float4*)d_in[2];
    const int*    nbmap      = (const int*)d_in[3];
    float*        out        = (float*)d_out;

    init_bias_kernel<<<(N_VOX * 8 + 255) / 256, 256>>>((float4*)out, bias4);
    conv_mma_kernel<<<GRID, TPB>>>(in_feature, kernel_w, nbmap, out);
}

// round 8
// speedup vs baseline: 1.1625x; 1.0449x over previous
#include <cuda_runtime.h>
#include <cstdint>

#define K3          27
#define PAIRS_PER_K 131072
#define N_VOX       262144
#define C_IN        32
#define C_OUT       32
#define M_TOTAL     (K3 * PAIRS_PER_K)

#define TILE        128                     // pairs per MMA tile (8 warps x 16)
#define NT          8                       // tiles per block (same k)
#define TPB         256
#define TILES_PER_K (PAIRS_PER_K / TILE)    // 1024 (divisible by NT)
#define GRID        (M_TOTAL / TILE / NT)   // 3456
#define RS          36                      // A smem row stride in floats (144B)

// ---------------------------------------------------------------------------
// Kernel 1: initialize output with bias (d_out is poisoned by harness).
// ---------------------------------------------------------------------------
__global__ void init_bias_kernel(float4* __restrict__ out,
                                 const float4* __restrict__ bias4) {
    int t = blockIdx.x * blockDim.x + threadIdx.x;
    if (t < N_VOX * 8) out[t] = bias4[t & 7];
}

__device__ __forceinline__ uint32_t f2tf32(float x) {
    uint32_t r;
    asm("cvt.rna.tf32.f32 %0, %1;" : "=r"(r) : "f"(x));
    return r;
}

// ---------------------------------------------------------------------------
// Kernel 2: cp.async gather -> ldmatrix A-frags -> tf32 mma.sync (m16n8k8;
// B frags j0-1 register-resident, j2-3 from a 2KB smem table) -> D staged to
// smem (A buffer reuse) -> line-coalesced red.global.add.v4 scatter.
// ---------------------------------------------------------------------------
__global__ void __launch_bounds__(TPB, 4)
conv_mma_kernel(const float* __restrict__ in_feature,   // [N_VOX][32]
                const float* __restrict__ kernel_w,     // [K3][32][32]
                const int*   __restrict__ nbmap,        // [M][2] (src,dst)
                float*       __restrict__ out)          // [N_VOX][32]
{
    __shared__ __align__(16) float As[2][TILE * RS];    // 2 x 18432B
    __shared__ __align__(16) uint2 Bsm[256];            // 2KB: j=2,3 frags

    const int tid  = threadIdx.x;
    const int wid  = tid >> 5;
    const int lane = tid & 31;

    const int tile0 = blockIdx.x * NT;
    const int k     = tile0 / TILES_PER_K;

    const float* wk = kernel_w + (size_t)k * (C_IN * C_OUT);
    const int bk = lane & 3, bn = lane >> 2;

    // ---- B fragments j=0,1 in registers (once per block, RNA tf32) ----
    uint32_t Breg[2][4][2];
#pragma unroll
    for (int j = 0; j < 2; j++)
#pragma unroll
        for (int s = 0; s < 4; s++) {
            Breg[j][s][0] = f2tf32(wk[(8 * s + bk    ) * C_OUT + 8 * j + bn]);
            Breg[j][s][1] = f2tf32(wk[(8 * s + bk + 4) * C_OUT + 8 * j + bn]);
        }
    // ---- B fragments j=2,3 in a per-lane smem table ----
    {
        const int e  = tid;                   // e = (j-2)*128 + s*32 + lane
        const int el = e & 31, s = (e >> 5) & 3, j = 2 + (e >> 7);
        const int ek = el & 3, en = el >> 2;
        uint2 b;
        b.x = f2tf32(wk[(8 * s + ek    ) * C_OUT + 8 * j + en]);
        b.y = f2tf32(wk[(8 * s + ek + 4) * C_OUT + 8 * j + en]);
        Bsm[e] = b;
    }

    // ---- gather tile t into buffer buf: 1024 x cp.async.cg 16B ----
    auto gather = [&](int t, int buf) {
        const size_t pbase = (size_t)(tile0 + t) * TILE;
        const int ch = tid & 7;
#pragma unroll
        for (int jj = 0; jj < 4; jj++) {
            const int row = (tid >> 3) + 32 * jj;
            const int v   = nbmap[2 * (pbase + row)];         // src voxel
            const uint32_t dst =
                (uint32_t)__cvta_generic_to_shared(&As[buf][row * RS + ch * 4]);
            asm volatile("cp.async.cg.shared.global [%0], [%1], 16;"
                         :: "r"(dst), "l"(in_feature + (size_t)v * C_IN + ch * 4));
        }
        asm volatile("cp.async.commit_group;" ::: "memory");
    };

    gather(0, 0);

    const int ar = lane >> 2;                       // frag row-in-8
    const int ac = lane & 3;                        // frag col-in-4
    // ldmatrix row/col mapping: lanes 0-7 -> a0 rows, 8-15 -> a1, 16-23 -> a2,
    // 24-31 -> a3:  row = 16*wid + (lane & 15), col-u32 = 8s + 4*(lane>>4).
    const int lm_row = 16 * wid + (lane & 15);
    const int lm_col = 4 * (lane >> 4);

    for (int t = 0; t < NT; t++) {
        const int buf = t & 1;
        asm volatile("cp.async.wait_group 0;" ::: "memory");
        __syncthreads();                            // A(t) + Bsm ready

        if (t + 1 < NT) gather(t + 1, buf ^ 1);     // overlap with compute

        // A fragments via ldmatrix.x4 (raw f32 bits = RZ tf32), one per k8.
        uint32_t A0[4], A1[4], A2[4], A3[4];
        const uint32_t abase = (uint32_t)__cvta_generic_to_shared(
            &As[buf][lm_row * RS + lm_col]);
#pragma unroll
        for (int s = 0; s < 4; s++) {
            asm volatile("ldmatrix.sync.aligned.m8n8.x4.shared.b16 "
                         "{%0,%1,%2,%3}, [%4];"
                         : "=r"(A0[s]), "=r"(A1[s]), "=r"(A2[s]), "=r"(A3[s])
                         : "r"(abase + 32 * s));    // +8 u32 cols per k-step
        }
        __syncwarp();   // all lanes' A reads done before D overwrites buffer

#pragma unroll
        for (int j = 0; j < 4; j++) {
            float D0 = 0.f, D1 = 0.f, D2 = 0.f, D3 = 0.f;
#pragma unroll
            for (int s = 0; s < 4; s++) {
                uint2 b;
                if (j < 2) { b.x = Breg[j][s][0]; b.y = Breg[j][s][1]; }
                else       { b = Bsm[(j - 2) * 128 + s * 32 + lane]; }
                asm volatile(
                    "mma.sync.aligned.m16n8k8.row.col.f32.tf32.tf32.f32 "
                    "{%0,%1,%2,%3}, {%4,%5,%6,%7}, {%8,%9}, {%0,%1,%2,%3};"
                    : "+f"(D0), "+f"(D1), "+f"(D2), "+f"(D3)
                    : "r"(A0[s]), "r"(A1[s]), "r"(A2[s]), "r"(A3[s]),
                      "r"(b.x), "r"(b.y));
            }
            // Stage D into the consumed A buffer (warp-private rows).
            *reinterpret_cast<float2*>(
                &As[buf][(16 * wid + ar)     * RS + 2 * ac + 8 * j]) =
                make_float2(D0, D1);
            *reinterpret_cast<float2*>(
                &As[buf][(16 * wid + ar + 8) * RS + 2 * ac + 8 * j]) =
                make_float2(D2, D3);
        }
        __syncwarp();

        // Line-coalesced scatter: lanes 0-7 cover one full 128B output row.
        const size_t pbase = (size_t)(tile0 + t) * TILE;
        const int chunk = lane & 7;
#pragma unroll
        for (int ii = 0; ii < 4; ii++) {
            const int row = 16 * wid + (lane >> 3) + 4 * ii;
            const int y   = nbmap[2 * (pbase + row) + 1];
            const float4 v = *reinterpret_cast<const float4*>(
                &As[buf][row * RS + chunk * 4]);
            asm volatile("red.global.add.v4.f32 [%0], {%1,%2,%3,%4};"
                         :: "l"(out + (size_t)y * C_OUT + chunk * 4),
                            "f"(v.x), "f"(v.y), "f"(v.z), "f"(v.w)
                         : "memory");
        }
    }
}

// ---------------------------------------------------------------------------
// Inputs (metadata order): in_feature f32[N_VOX,32], kernel f32[27,32,32],
// bias f32[32], nbmap i32[M,2], nbsizes i32[27]. Output f32[N_VOX,32].
// ---------------------------------------------------------------------------
extern "C" void kernel_launch(void* const* d_in, const int* in_sizes, int n_in,
                              void* d_out, int out_size) {
    const float*  in_feature = (const float*)d_in[0];
    const float*  kernel_w   = (const float*)d_in[1];
    const float4* bias4      = (const float4*)d_in[2];
    const int*    nbmap      = (const int*)d_in[3];
    float*        out        = (float*)d_out;

    init_bias_kernel<<<(N_VOX * 8 + 255) / 256, 256>>>((float4*)out, bias4);
    conv_mma_kernel<<<GRID, TPB>>>(in_feature, kernel_w, nbmap, out);
}